// round 11
// baseline (speedup 1.0000x reference)
#include <cuda_runtime.h>
#include <cstdint>

#define FM      14
#define HW      196          // 14*14
#define CH      2048
#define CHUNKS  16
#define CPC     (CH / CHUNKS)   // 128 channels per chunk
#define NPAIR   (CPC / 2)       // 64 channel-pairs per chunk
#define NWIN    361
#define MAXB    64

#define NEG_INF __int_as_float(0xff800000)

// Partial channel sums: [chunk][batch][hw]. Fully overwritten every run.
__device__ float g_part[CHUNKS * MAXB * HW];
// Per-batch arrival counters. Zero at load; reset by consumer each run.
__device__ int g_count[MAXB];

__device__ __forceinline__ int atom_add_release_gpu(int* p, int v) {
    int old;
    asm volatile("atom.add.release.gpu.global.s32 %0, [%1], %2;"
                 : "=r"(old) : "l"(p), "r"(v) : "memory");
    return old;
}
__device__ __forceinline__ int ld_acquire_gpu(const int* p) {
    int v;
    asm volatile("ld.acquire.gpu.global.s32 %0, [%1];" : "=r"(v) : "l"(p) : "memory");
    return v;
}
// 256-bit high-L2-retention load (sm_100: evict_last requires v8.b32).
__device__ __forceinline__ void ldg256_evict_last(uint32_t* t, const float* p) {
    asm volatile("ld.global.nc.L2::evict_last.v8.b32 "
                 "{%0,%1,%2,%3,%4,%5,%6,%7}, [%8];"
                 : "=r"(t[0]), "=r"(t[1]), "=r"(t[2]), "=r"(t[3]),
                   "=r"(t[4]), "=r"(t[5]), "=r"(t[6]), "=r"(t[7])
                 : "l"(p));
}
// Streaming (low-retention) store for the once-read partials.
__device__ __forceinline__ void st_streaming(float* p, float v) {
    asm volatile("st.global.cs.f32 [%0], %1;" :: "l"(p), "f"(v) : "memory");
}

__device__ __forceinline__ float pick4(const float a[4], int kk) {
    float r = a[0];
    if (kk == 1) r = a[1];
    if (kk == 2) r = a[2];
    if (kk == 3) r = a[3];
    return r;
}

// ---------------------------------------------------------------------------
// Kernel 1: streaming reduction with LDG.256 + L2::evict_last, PDL trigger,
// release-atomic arrival. Channel-PAIRS (392 floats = 49 x 32B units) so the
// 256-bit loads tile exactly; lane (v,k) always feeds spatial position
// (v*8+k) mod 196, resolved in the shared reduction.
// ---------------------------------------------------------------------------
__global__ __launch_bounds__(196) void chan_sum_kernel(const float* __restrict__ x, int B) {
    asm volatile("griddepcontrol.launch_dependents;" ::: "memory");

    const int b     = blockIdx.x;
    const int chunk = blockIdx.y;
    const int tid   = threadIdx.x;          // 0..195
    const int grp   = tid / 49;             // 0..3
    const int v     = tid - grp * 49;       // 0..48

    const float* cb = x + ((size_t)b * CH + (size_t)chunk * CPC) * HW;

    float acc[8] = {0.f, 0.f, 0.f, 0.f, 0.f, 0.f, 0.f, 0.f};
#pragma unroll 4
    for (int cp = grp; cp < NPAIR; cp += 4) {
        uint32_t t[8];
        ldg256_evict_last(t, cb + (size_t)cp * 392 + v * 8);
#pragma unroll
        for (int k = 0; k < 8; k++) acc[k] += __uint_as_float(t[k]);
    }

    __shared__ float red[4 * 392];   // 6272 B
    {
        float* dst = &red[grp * 392 + v * 8];
#pragma unroll
        for (int k = 0; k < 8; k++) dst[k] = acc[k];
    }
    __syncthreads();

    if (tid < HW) {
        float s = 0.f;
#pragma unroll
        for (int g = 0; g < 4; g++)
            s += red[g * 392 + tid] + red[g * 392 + tid + HW];
        st_streaming(&g_part[(chunk * B + b) * HW + tid], s);
    }
    __syncthreads();
    if (tid == 0) (void)atom_add_release_gpu(&g_count[b], 1);
}

// ---------------------------------------------------------------------------
// Kernel 2: finalize (PDL co-scheduled). One block per batch; spins on its
// batch's arrival counter, then partial-sum, window scores, NMS, outputs.
// Output layout (fp32): [B*7 indices][B*7 window scores][B*361 all_scores]
// ---------------------------------------------------------------------------
__global__ __launch_bounds__(384) void appm_finalize_kernel(
    const int* __restrict__ coords, float* __restrict__ out, int B)
{
    const int b   = blockIdx.x;
    const int tid = threadIdx.x;

    __shared__ float ssum[HW];
    __shared__ float scores[NWIN];
    __shared__ float cbox[NWIN * 4];
    __shared__ int   sel_idx[7];
    __shared__ float sel_sc[7];

    for (int i = tid; i < NWIN * 4; i += blockDim.x) cbox[i] = (float)coords[i];

    if (tid == 0) {
        while (ld_acquire_gpu(&g_count[b]) < CHUNKS) __nanosleep(32);
        g_count[b] = 0;   // reset for next graph replay
    }
    __syncthreads();

    if (tid < HW) {
        float s = 0.f;
#pragma unroll
        for (int k = 0; k < CHUNKS; k++) s += __ldcg(&g_part[(k * B + b) * HW + tid]);
        ssum[tid] = s;
    }
    __syncthreads();

    float* all_scores_out = out + 14 * B;   // after indices[B*7] + scores[B*7]
    for (int w = tid; w < NWIN; w += blockDim.x) {
        int i, j, rh, rw;
        if (w < 121)      { rh = 4; rw = 4; int l = w;       i = l / 11; j = l % 11; }
        else if (w < 241) { rh = 3; rw = 5; int l = w - 121; i = l / 10; j = l % 10; }
        else              { rh = 5; rw = 3; int l = w - 241; i = l / 12; j = l % 12; }
        float s = 0.f;
        for (int di = 0; di < rh; di++)
            for (int dj = 0; dj < rw; dj++)
                s += ssum[(i + di) * FM + (j + dj)];
        s /= (float)(rh * rw);
        scores[w] = s;
        all_scores_out[b * NWIN + w] = s;
    }
    __syncthreads();

    const int wid  = tid >> 5;
    const int lane = tid & 31;
    if (wid < 3) {
        const int starts[3] = {0, 121, 241};
        const int counts[3] = {121, 120, 120};
        const int ns[3]     = {2, 3, 2};
        const int outoff[3] = {0, 2, 5};
        const float thresh  = 0.25f;

        const int st  = starts[wid];
        const int cnt = counts[wid];
        const int n   = ns[wid];

        float sc[4], x0[4], y0[4], x1[4], y1[4];
        bool  alive[4];
#pragma unroll
        for (int k = 0; k < 4; k++) {
            int ii = k * 32 + lane;
            bool valid = (ii < cnt);
            alive[k] = valid;
            int gi = st + (valid ? ii : 0);
            sc[k] = valid ? scores[gi] : 0.f;
            x0[k] = cbox[gi * 4 + 0];
            y0[k] = cbox[gi * 4 + 1];
            x1[k] = cbox[gi * 4 + 2];
            y1[k] = cbox[gi * 4 + 3];
        }

        for (int step = 0; step < n; step++) {
            float bv = NEG_INF;
            int   bi = 0x7FFFFFFF;
#pragma unroll
            for (int k = 0; k < 4; k++) {
                float vkv = alive[k] ? sc[k] : NEG_INF;
                int   vki = k * 32 + lane;
                if (vki < cnt && (vkv > bv || (vkv == bv && vki < bi))) { bv = vkv; bi = vki; }
            }
#pragma unroll
            for (int off = 16; off > 0; off >>= 1) {
                float ov = __shfl_down_sync(0xFFFFFFFFu, bv, off);
                int   oi = __shfl_down_sync(0xFFFFFFFFu, bi, off);
                if (ov > bv || (ov == bv && oi < bi)) { bv = ov; bi = oi; }
            }
            bi = __shfl_sync(0xFFFFFFFFu, bi, 0);

            if (lane == 0) {
                sel_idx[outoff[wid] + step] = st + bi;
                sel_sc [outoff[wid] + step] = scores[st + bi];
            }

            const int kk = bi >> 5;
            const int srcLane = bi & 31;
            float BX0 = __shfl_sync(0xFFFFFFFFu, pick4(x0, kk), srcLane);
            float BY0 = __shfl_sync(0xFFFFFFFFu, pick4(y0, kk), srcLane);
            float BX1 = __shfl_sync(0xFFFFFFFFu, pick4(x1, kk), srcLane);
            float BY1 = __shfl_sync(0xFFFFFFFFu, pick4(y1, kk), srcLane);
            float areaB = (BX1 - BX0) * (BY1 - BY0);

#pragma unroll
            for (int k = 0; k < 4; k++) {
                float ix0 = fmaxf(BX0, x0[k]);
                float iy0 = fmaxf(BY0, y0[k]);
                float ix1 = fminf(BX1, x1[k]);
                float iy1 = fminf(BY1, y1[k]);
                float inter = fmaxf(ix1 - ix0, 0.f) * fmaxf(iy1 - iy0, 0.f);
                float areaK = (x1[k] - x0[k]) * (y1[k] - y0[k]);
                float iou = inter / (areaB + areaK - inter);
                if (!(iou < thresh)) alive[k] = false;
            }
        }
    }
    __syncthreads();

    if (tid < 7) {
        out[b * 7 + tid]         = (float)sel_idx[tid];
        out[7 * B + b * 7 + tid] = sel_sc[tid];
    }
}

extern "C" void kernel_launch(void* const* d_in, const int* in_sizes, int n_in,
                              void* d_out, int out_size) {
    const float* x      = (const float*)d_in[0];
    const int*   coords = (const int*)d_in[1];
    float*       out    = (float*)d_out;

    const int B = in_sizes[0] / (CH * HW);   // 64

    dim3 grid1(B, CHUNKS);
    chan_sum_kernel<<<grid1, 196>>>(x, B);

    cudaLaunchConfig_t cfg = {};
    cfg.gridDim  = dim3(B, 1, 1);
    cfg.blockDim = dim3(384, 1, 1);
    cfg.dynamicSmemBytes = 0;
    cfg.stream = 0;
    cudaLaunchAttribute attrs[1];
    attrs[0].id = cudaLaunchAttributeProgrammaticStreamSerialization;
    attrs[0].val.programmaticStreamSerializationAllowed = 1;
    cfg.attrs = attrs;
    cfg.numAttrs = 1;

    cudaError_t err = cudaLaunchKernelEx(&cfg, appm_finalize_kernel, coords, out, B);
    if (err != cudaSuccess) {
        (void)cudaGetLastError();   // clear
        appm_finalize_kernel<<<B, 384>>>(coords, out, B);
    }
}

// round 12
// speedup vs baseline: 1.1400x; 1.1400x over previous
#include <cuda_runtime.h>
#include <cstdint>

#define FM      14
#define HW      196          // 14*14
#define CH      2048
#define CHUNKS  16
#define CPC     (CH / CHUNKS)   // 128 channels per chunk
#define NWIN    361
#define MAXB    64

#define NEG_INF __int_as_float(0xff800000)

// Per-batch channel sums, accumulated via RED.ADD.F32 by the 16 chunk blocks.
// Zero at load; reset to zero by the finalize kernel each run.
__device__ float g_sum[MAXB * HW];
// Per-batch arrival counters. Zero at load; reset by finalize each run.
__device__ int g_count[MAXB];

__device__ __forceinline__ int atom_add_release_gpu(int* p, int v) {
    int old;
    asm volatile("atom.add.release.gpu.global.s32 %0, [%1], %2;"
                 : "=r"(old) : "l"(p), "r"(v) : "memory");
    return old;
}
__device__ __forceinline__ int ld_acquire_gpu(const int* p) {
    int v;
    asm volatile("ld.acquire.gpu.global.s32 %0, [%1];" : "=r"(v) : "l"(p) : "memory");
    return v;
}
__device__ __forceinline__ void red_add_f32(float* p, float v) {
    asm volatile("red.global.add.f32 [%0], %1;" :: "l"(p), "f"(v) : "memory");
}

__device__ __forceinline__ float pick4(const float a[4], int kk) {
    float r = a[0];
    if (kk == 1) r = a[1];
    if (kk == 2) r = a[2];
    if (kk == 3) r = a[3];
    return r;
}

// ---------------------------------------------------------------------------
// Kernel 1: lean streaming reduction (exact R9 form: LDG.128, unroll 8, no
// hints, no launch_bounds cap) + PDL trigger + RED.ADD accumulation into the
// per-batch sum + one release-atomic arrival.
// ---------------------------------------------------------------------------
__global__ __launch_bounds__(196) void chan_sum_kernel(const float* __restrict__ x, int B) {
    asm volatile("griddepcontrol.launch_dependents;" ::: "memory");

    const int b     = blockIdx.x;
    const int chunk = blockIdx.y;
    const int tid   = threadIdx.x;          // 0..195
    const int grp   = tid / 49;             // 0..3
    const int v     = tid - grp * 49;       // 0..48

    const float4* base = reinterpret_cast<const float4*>(
        x + ((size_t)b * CH + (size_t)chunk * CPC) * HW);

    float4 acc = make_float4(0.f, 0.f, 0.f, 0.f);
#pragma unroll 8
    for (int c = grp; c < CPC; c += 4) {
        float4 t = base[c * 49 + v];
        acc.x += t.x; acc.y += t.y; acc.z += t.z; acc.w += t.w;
    }

    __shared__ float4 red[4 * 49];
    red[grp * 49 + v] = acc;
    __syncthreads();

    if (tid < HW) {
        const float* rf = reinterpret_cast<const float*>(red);
        red_add_f32(&g_sum[b * HW + tid],
                    rf[tid] + rf[HW + tid] + rf[2 * HW + tid] + rf[3 * HW + tid]);
    }
    __syncthreads();
    if (tid == 0) (void)atom_add_release_gpu(&g_count[b], 1);
}

// ---------------------------------------------------------------------------
// Kernel 2: finalize (PDL co-scheduled). One block per batch; spins on its
// batch's arrival counter, reads the accumulated sum directly, then window
// scores, greedy NMS, outputs. Resets g_sum/g_count for the next replay.
// Output layout (fp32): [B*7 indices][B*7 window scores][B*361 all_scores]
// ---------------------------------------------------------------------------
__global__ __launch_bounds__(384) void appm_finalize_kernel(
    const int* __restrict__ coords, float* __restrict__ out, int B)
{
    const int b   = blockIdx.x;
    const int tid = threadIdx.x;

    __shared__ float ssum[HW];
    __shared__ float scores[NWIN];
    __shared__ float cbox[NWIN * 4];
    __shared__ int   sel_idx[7];
    __shared__ float sel_sc[7];

    for (int i = tid; i < NWIN * 4; i += blockDim.x) cbox[i] = (float)coords[i];

    if (tid == 0) {
        while (ld_acquire_gpu(&g_count[b]) < CHUNKS) __nanosleep(32);
        g_count[b] = 0;   // reset for next graph replay
    }
    __syncthreads();

    if (tid < HW) {
        ssum[tid] = __ldcg(&g_sum[b * HW + tid]);
        g_sum[b * HW + tid] = 0.f;   // reset for next graph replay
    }
    __syncthreads();

    float* all_scores_out = out + 14 * B;   // after indices[B*7] + scores[B*7]
    for (int w = tid; w < NWIN; w += blockDim.x) {
        int i, j, rh, rw;
        if (w < 121)      { rh = 4; rw = 4; int l = w;       i = l / 11; j = l % 11; }
        else if (w < 241) { rh = 3; rw = 5; int l = w - 121; i = l / 10; j = l % 10; }
        else              { rh = 5; rw = 3; int l = w - 241; i = l / 12; j = l % 12; }
        float s = 0.f;
        for (int di = 0; di < rh; di++)
            for (int dj = 0; dj < rw; dj++)
                s += ssum[(i + di) * FM + (j + dj)];
        s /= (float)(rh * rw);
        scores[w] = s;
        all_scores_out[b * NWIN + w] = s;
    }
    __syncthreads();

    const int wid  = tid >> 5;
    const int lane = tid & 31;
    if (wid < 3) {
        const int starts[3] = {0, 121, 241};
        const int counts[3] = {121, 120, 120};
        const int ns[3]     = {2, 3, 2};
        const int outoff[3] = {0, 2, 5};
        const float thresh  = 0.25f;

        const int st  = starts[wid];
        const int cnt = counts[wid];
        const int n   = ns[wid];

        float sc[4], x0[4], y0[4], x1[4], y1[4];
        bool  alive[4];
#pragma unroll
        for (int k = 0; k < 4; k++) {
            int ii = k * 32 + lane;
            bool valid = (ii < cnt);
            alive[k] = valid;
            int gi = st + (valid ? ii : 0);
            sc[k] = valid ? scores[gi] : 0.f;
            x0[k] = cbox[gi * 4 + 0];
            y0[k] = cbox[gi * 4 + 1];
            x1[k] = cbox[gi * 4 + 2];
            y1[k] = cbox[gi * 4 + 3];
        }

        for (int step = 0; step < n; step++) {
            float bv = NEG_INF;
            int   bi = 0x7FFFFFFF;
#pragma unroll
            for (int k = 0; k < 4; k++) {
                float vkv = alive[k] ? sc[k] : NEG_INF;
                int   vki = k * 32 + lane;
                if (vki < cnt && (vkv > bv || (vkv == bv && vki < bi))) { bv = vkv; bi = vki; }
            }
#pragma unroll
            for (int off = 16; off > 0; off >>= 1) {
                float ov = __shfl_down_sync(0xFFFFFFFFu, bv, off);
                int   oi = __shfl_down_sync(0xFFFFFFFFu, bi, off);
                if (ov > bv || (ov == bv && oi < bi)) { bv = ov; bi = oi; }
            }
            bi = __shfl_sync(0xFFFFFFFFu, bi, 0);

            if (lane == 0) {
                sel_idx[outoff[wid] + step] = st + bi;
                sel_sc [outoff[wid] + step] = scores[st + bi];
            }

            const int kk = bi >> 5;
            const int srcLane = bi & 31;
            float BX0 = __shfl_sync(0xFFFFFFFFu, pick4(x0, kk), srcLane);
            float BY0 = __shfl_sync(0xFFFFFFFFu, pick4(y0, kk), srcLane);
            float BX1 = __shfl_sync(0xFFFFFFFFu, pick4(x1, kk), srcLane);
            float BY1 = __shfl_sync(0xFFFFFFFFu, pick4(y1, kk), srcLane);
            float areaB = (BX1 - BX0) * (BY1 - BY0);

#pragma unroll
            for (int k = 0; k < 4; k++) {
                float ix0 = fmaxf(BX0, x0[k]);
                float iy0 = fmaxf(BY0, y0[k]);
                float ix1 = fminf(BX1, x1[k]);
                float iy1 = fminf(BY1, y1[k]);
                float inter = fmaxf(ix1 - ix0, 0.f) * fmaxf(iy1 - iy0, 0.f);
                float areaK = (x1[k] - x0[k]) * (y1[k] - y0[k]);
                float iou = inter / (areaB + areaK - inter);
                if (!(iou < thresh)) alive[k] = false;
            }
        }
    }
    __syncthreads();

    if (tid < 7) {
        out[b * 7 + tid]         = (float)sel_idx[tid];
        out[7 * B + b * 7 + tid] = sel_sc[tid];
    }
}

extern "C" void kernel_launch(void* const* d_in, const int* in_sizes, int n_in,
                              void* d_out, int out_size) {
    const float* x      = (const float*)d_in[0];
    const int*   coords = (const int*)d_in[1];
    float*       out    = (float*)d_out;

    const int B = in_sizes[0] / (CH * HW);   // 64

    dim3 grid1(B, CHUNKS);
    chan_sum_kernel<<<grid1, 196>>>(x, B);

    cudaLaunchConfig_t cfg = {};
    cfg.gridDim  = dim3(B, 1, 1);
    cfg.blockDim = dim3(384, 1, 1);
    cfg.dynamicSmemBytes = 0;
    cfg.stream = 0;
    cudaLaunchAttribute attrs[1];
    attrs[0].id = cudaLaunchAttributeProgrammaticStreamSerialization;
    attrs[0].val.programmaticStreamSerializationAllowed = 1;
    cfg.attrs = attrs;
    cfg.numAttrs = 1;

    cudaError_t err = cudaLaunchKernelEx(&cfg, appm_finalize_kernel, coords, out, B);
    if (err != cudaSuccess) {
        (void)cudaGetLastError();   // clear
        appm_finalize_kernel<<<B, 384>>>(coords, out, B);
    }
}